// round 3
// baseline (speedup 1.0000x reference)
#include <cuda_runtime.h>
#include <cstdint>

#define B_   128
#define T_   32
#define NS_  200
#define ROWS_TOTAL (B_*NS_)     // 25600
#define HID_ 64
#define G_   256                // 4*HID gates
#define RPB  48                 // rows per block
#define NGRP (RPB/4)            // 12 groups of 4 rows
#define NBLK ((ROWS_TOTAL + RPB - 1)/RPB)   // 534
#define TPB  256
#define HST  68                 // padded h row stride (floats), 272B = 16B-aligned

// ---------------- scratch (static device allocations are allowed) ----------------
__device__ float g_xproj[B_*T_*G_];          // 4 MB
__device__ float g_eps[T_*ROWS_TOTAL];       // 3.125 MB

// ---------------- helpers ----------------
__device__ __forceinline__ uint32_t rotl32(uint32_t x, int d){ return (x<<d)|(x>>(32-d)); }

__device__ __forceinline__ float sigmoidf_(float x){ return 1.0f/(1.0f+expf(-x)); }
__device__ __forceinline__ float softplusf_(float x){ return fmaxf(x,0.0f) + log1pf(expf(-fabsf(x))); }

// XLA f32 ErfInv (Giles), exactly the polynomial JAX lowers to
__device__ __forceinline__ float erfinv_xla(float x){
  float w = -log1pf(-x*x);
  float p;
  if (w < 5.0f) {
    w = w - 2.5f;
    p = 2.81022636e-08f;
    p = fmaf(p, w, 3.43273939e-07f);
    p = fmaf(p, w, -3.5233877e-06f);
    p = fmaf(p, w, -4.39150654e-06f);
    p = fmaf(p, w, 0.00021858087f);
    p = fmaf(p, w, -0.00125372503f);
    p = fmaf(p, w, -0.00417768164f);
    p = fmaf(p, w, 0.246640727f);
    p = fmaf(p, w, 1.50140941f);
  } else {
    w = sqrtf(w) - 3.0f;
    p = -0.000200214257f;
    p = fmaf(p, w, 0.000100950558f);
    p = fmaf(p, w, 0.00134934322f);
    p = fmaf(p, w, -0.00367342844f);
    p = fmaf(p, w, 0.00573950773f);
    p = fmaf(p, w, -0.0076224613f);
    p = fmaf(p, w, 0.00943887047f);
    p = fmaf(p, w, 1.00167406f);
    p = fmaf(p, w, 2.83297682f);
  }
  return p * x;
}

__device__ __forceinline__ float bits_to_normal(uint32_t bits){
  // jax.random.uniform: ((bits>>9)|one_bits -> [1,2)) - 1 in [0,1); scale to [nextafter(-1,0), 1)
  float u = __uint_as_float((bits>>9) | 0x3f800000u) - 1.0f;
  // (hi-lo) rounds to exactly 2.0f in f32; lo = -0x1.fffffep-1
  float x = fmaf(u, 2.0f, -0.99999994f);
  x = fmaxf(-0.99999994f, x);
  return 1.41421356f * erfinv_xla(x);   // sqrt(2) in f32
}

// ---------------- kernel B: eps = jax.random.normal(key(42), (T, B*ns)) ----------------
// Partitionable Threefry (default since JAX 0.4.36): counter-mode per element.
// Element j: cipher input (counts_hi, counts_lo) = (0, j); for bit_width 32 the
// result is convert_element_type(bits1 ^ bits2, uint32) — XOR of BOTH output words.
__global__ void eps_kernel(){
  const uint32_t N = (uint32_t)(T_*ROWS_TOTAL);   // 819200
  uint32_t j = blockIdx.x*blockDim.x + threadIdx.x;
  if (j >= N) return;
  const uint32_t ks0 = 0u, ks1 = 42u, ks2 = 0x1BD11BDAu ^ 42u;
  uint32_t x0 = 0u, x1 = j;
  x0 += ks0; x1 += ks1;
#define RND_(r) { x0 += x1; x1 = rotl32(x1, (r)); x1 ^= x0; }
  RND_(13) RND_(15) RND_(26) RND_(6)   x0 += ks1; x1 += ks2 + 1u;
  RND_(17) RND_(29) RND_(16) RND_(24)  x0 += ks2; x1 += ks0 + 2u;
  RND_(13) RND_(15) RND_(26) RND_(6)   x0 += ks0; x1 += ks1 + 3u;
  RND_(17) RND_(29) RND_(16) RND_(24)  x0 += ks1; x1 += ks2 + 4u;
  RND_(13) RND_(15) RND_(26) RND_(6)   x0 += ks2; x1 += ks0 + 5u;
#undef RND_
  g_eps[j] = bits_to_normal(x0 ^ x1);   // bits1 ^ bits2
}

// ---------------- kernel A: xproj[b][t][g] (features 1..31 + both layer0 biases) ----------------
__global__ void xproj_kernel(const float* __restrict__ dec_cont,
                             const float* __restrict__ emb0,
                             const float* __restrict__ emb1,
                             const float* __restrict__ Wih0,
                             const float* __restrict__ bih0,
                             const float* __restrict__ bhh0,
                             const int*   __restrict__ dec_cat){
  int bt = blockIdx.x;            // 0..4095 (= b*T + t)
  int g  = threadIdx.x;           // 0..255
  __shared__ float feat[32];
  if (g < 32) {
    float v = 0.0f;
    if (g >= 1 && g < 6) {
      v = dec_cont[bt*6 + g];
    } else if (g >= 6 && g < 16) {
      int c0 = dec_cat[bt*2 + 0];
      v = emb0[c0*10 + (g-6)];
    } else if (g >= 16) {
      int c1 = dec_cat[bt*2 + 1];
      v = emb1[c1*16 + (g-16)];
    }
    feat[g] = v;
  }
  __syncthreads();
  float acc = bih0[g] + bhh0[g];
  #pragma unroll
  for (int k = 1; k < 32; k++) acc = fmaf(Wih0[g*32 + k], feat[k], acc);
  g_xproj[bt*G_ + g] = acc;
}

// ---------------- main persistent LSTM kernel ----------------
__global__ __launch_bounds__(TPB, 1)
void deepar_kernel(const float* __restrict__ ts,
                   const float* __restrict__ one_off,
                   const float* __restrict__ Wih0,
                   const float* __restrict__ Whh0,
                   const float* __restrict__ Wih1,
                   const float* __restrict__ Whh1,
                   const float* __restrict__ bih1,
                   const float* __restrict__ bhh1,
                   const float* __restrict__ Wproj,
                   const float* __restrict__ bproj,
                   const float* __restrict__ h0in,
                   const float* __restrict__ c0in,
                   float* __restrict__ out)
{
  extern __shared__ float sm[];
  float* sWhh0 = sm;                    // [64][256] k-major
  float* sWih1 = sm + 16384;            // [64][256] k-major
  float* sWhh1 = sm + 32768;            // [64][256] k-major
  float* sH0   = sm + 49152;            // [RPB][HST]
  float* sH1   = sH0 + RPB*HST;         // [RPB][HST]
  float* sG    = sH1 + RPB*HST;         // [4][256] gate exchange
  float* sC0w  = sG + 1024;             // Wih0 column 0 [256]
  float* sB1   = sC0w + 256;            // combined layer1 bias [256]
  float* sWp   = sB1 + 256;             // Wproj[2][64] + bproj[2]  (130)
  float* sLag  = sWp + 130;             // [RPB]
  float* sCen  = sLag + RPB;            // [RPB]
  float* sScl  = sCen + RPB;            // [RPB]
  float* sP    = sScl + RPB;            // [2*RPB]

  const int tid  = threadIdx.x;
  const int blk  = blockIdx.x;
  const int row0 = blk * RPB;
  int nrows = ROWS_TOTAL - row0; if (nrows > RPB) nrows = RPB;

  // --- load weights k-major ---
  {
    const int g = tid;
    #pragma unroll
    for (int kc = 0; kc < 16; kc++) {
      float4 a = *(const float4*)&Whh0[g*64 + kc*4];
      sWhh0[(kc*4+0)*G_+g]=a.x; sWhh0[(kc*4+1)*G_+g]=a.y;
      sWhh0[(kc*4+2)*G_+g]=a.z; sWhh0[(kc*4+3)*G_+g]=a.w;
      float4 b = *(const float4*)&Wih1[g*64 + kc*4];
      sWih1[(kc*4+0)*G_+g]=b.x; sWih1[(kc*4+1)*G_+g]=b.y;
      sWih1[(kc*4+2)*G_+g]=b.z; sWih1[(kc*4+3)*G_+g]=b.w;
      float4 c = *(const float4*)&Whh1[g*64 + kc*4];
      sWhh1[(kc*4+0)*G_+g]=c.x; sWhh1[(kc*4+1)*G_+g]=c.y;
      sWhh1[(kc*4+2)*G_+g]=c.z; sWhh1[(kc*4+3)*G_+g]=c.w;
    }
    sC0w[g] = Wih0[g*32];
    sB1[g]  = bih1[g] + bhh1[g];
  }
  if (tid < 128) sWp[tid] = Wproj[tid];
  if (tid < 2)   sWp[128+tid] = bproj[tid];

  // --- init h state (zero for padded rows) ---
  for (int idx = tid; idx < RPB*HID_; idx += TPB) {
    int lr = idx >> 6, ch = idx & 63;
    float v0 = 0.0f, v1 = 0.0f;
    if (lr < nrows) {
      int b = (row0 + lr)/NS_;
      v0 = h0in[b*HID_ + ch];
      v1 = h0in[B_*HID_ + b*HID_ + ch];
    }
    sH0[lr*HST + ch] = v0;
    sH1[lr*HST + ch] = v1;
  }
  if (tid < RPB) {
    int lr = tid;
    if (lr < nrows) {
      int b = (row0 + lr)/NS_;
      sCen[lr] = ts[2*b];
      sScl[lr] = ts[2*b+1];
      sLag[lr] = one_off[b];
    } else { sCen[lr]=0.0f; sScl[lr]=1.0f; sLag[lr]=0.0f; }
  }

  // --- c state in registers ---
  const int sr = tid >> 6, ch = tid & 63;
  float c0r[NGRP], c1r[NGRP];
  #pragma unroll
  for (int gi = 0; gi < NGRP; gi++) {
    int lr = gi*4 + sr;
    float v0 = 0.0f, v1 = 0.0f;
    if (lr < nrows) {
      int b = (row0 + lr)/NS_;
      v0 = c0in[b*HID_ + ch];
      v1 = c0in[B_*HID_ + b*HID_ + ch];
    }
    c0r[gi] = v0; c1r[gi] = v1;
  }
  __syncthreads();

  // --- time loop ---
  #pragma unroll 1
  for (int t = 0; t < T_; t++) {
    #pragma unroll 1
    for (int gi = 0; gi < NGRP; gi++) {
      const int lr0 = gi*4;
      const int g = tid;
      float acc0, acc1, acc2, acc3;
      // layer0: xproj + Wih0[:,0]*lagged + Whh0 @ h0
      {
        int r0 = row0 + lr0;     int b0 = (r0 < ROWS_TOTAL ? r0 : ROWS_TOTAL-1)/NS_;
        int r1 = row0 + lr0 + 1; int b1 = (r1 < ROWS_TOTAL ? r1 : ROWS_TOTAL-1)/NS_;
        int r2 = row0 + lr0 + 2; int b2 = (r2 < ROWS_TOTAL ? r2 : ROWS_TOTAL-1)/NS_;
        int r3 = row0 + lr0 + 3; int b3 = (r3 < ROWS_TOTAL ? r3 : ROWS_TOTAL-1)/NS_;
        float w0c = sC0w[g];
        acc0 = fmaf(w0c, sLag[lr0+0], g_xproj[(b0*T_+t)*G_ + g]);
        acc1 = fmaf(w0c, sLag[lr0+1], g_xproj[(b1*T_+t)*G_ + g]);
        acc2 = fmaf(w0c, sLag[lr0+2], g_xproj[(b2*T_+t)*G_ + g]);
        acc3 = fmaf(w0c, sLag[lr0+3], g_xproj[(b3*T_+t)*G_ + g]);
      }
      {
        const float* ha = &sH0[(lr0+0)*HST];
        const float* hb = &sH0[(lr0+1)*HST];
        const float* hc = &sH0[(lr0+2)*HST];
        const float* hd = &sH0[(lr0+3)*HST];
        #pragma unroll
        for (int k = 0; k < HID_; k += 4) {
          float w0 = sWhh0[(k+0)*G_+g], w1 = sWhh0[(k+1)*G_+g];
          float w2 = sWhh0[(k+2)*G_+g], w3 = sWhh0[(k+3)*G_+g];
          float4 va = *(const float4*)&ha[k];
          float4 vb = *(const float4*)&hb[k];
          float4 vc = *(const float4*)&hc[k];
          float4 vd = *(const float4*)&hd[k];
          acc0 = fmaf(w0,va.x,acc0); acc0 = fmaf(w1,va.y,acc0); acc0 = fmaf(w2,va.z,acc0); acc0 = fmaf(w3,va.w,acc0);
          acc1 = fmaf(w0,vb.x,acc1); acc1 = fmaf(w1,vb.y,acc1); acc1 = fmaf(w2,vb.z,acc1); acc1 = fmaf(w3,vb.w,acc1);
          acc2 = fmaf(w0,vc.x,acc2); acc2 = fmaf(w1,vc.y,acc2); acc2 = fmaf(w2,vc.z,acc2); acc2 = fmaf(w3,vc.w,acc2);
          acc3 = fmaf(w0,vd.x,acc3); acc3 = fmaf(w1,vd.y,acc3); acc3 = fmaf(w2,vd.z,acc3); acc3 = fmaf(w3,vd.w,acc3);
        }
      }
      sG[       g] = acc0; sG[  G_ + g] = acc1;
      sG[2*G_ + g] = acc2; sG[3*G_ + g] = acc3;
      __syncthreads();
      // h0/c0 update
      {
        int lr = lr0 + sr;
        float gi_ = sG[sr*G_ + ch];
        float gf  = sG[sr*G_ + 64 + ch];
        float gg  = sG[sr*G_ + 128 + ch];
        float go  = sG[sr*G_ + 192 + ch];
        float c = sigmoidf_(gf)*c0r[gi] + sigmoidf_(gi_)*tanhf(gg);
        c0r[gi] = c;
        sH0[lr*HST + ch] = sigmoidf_(go)*tanhf(c);
      }
      __syncthreads();
      // layer1 gates: Wih1 @ h0_new + Whh1 @ h1_old + bias1
      acc0 = acc1 = acc2 = acc3 = sB1[g];
      {
        const float* ha = &sH0[(lr0+0)*HST];
        const float* hb = &sH0[(lr0+1)*HST];
        const float* hc = &sH0[(lr0+2)*HST];
        const float* hd = &sH0[(lr0+3)*HST];
        #pragma unroll
        for (int k = 0; k < HID_; k += 4) {
          float w0 = sWih1[(k+0)*G_+g], w1 = sWih1[(k+1)*G_+g];
          float w2 = sWih1[(k+2)*G_+g], w3 = sWih1[(k+3)*G_+g];
          float4 va = *(const float4*)&ha[k];
          float4 vb = *(const float4*)&hb[k];
          float4 vc = *(const float4*)&hc[k];
          float4 vd = *(const float4*)&hd[k];
          acc0 = fmaf(w0,va.x,acc0); acc0 = fmaf(w1,va.y,acc0); acc0 = fmaf(w2,va.z,acc0); acc0 = fmaf(w3,va.w,acc0);
          acc1 = fmaf(w0,vb.x,acc1); acc1 = fmaf(w1,vb.y,acc1); acc1 = fmaf(w2,vb.z,acc1); acc1 = fmaf(w3,vb.w,acc1);
          acc2 = fmaf(w0,vc.x,acc2); acc2 = fmaf(w1,vc.y,acc2); acc2 = fmaf(w2,vc.z,acc2); acc2 = fmaf(w3,vc.w,acc2);
          acc3 = fmaf(w0,vd.x,acc3); acc3 = fmaf(w1,vd.y,acc3); acc3 = fmaf(w2,vd.z,acc3); acc3 = fmaf(w3,vd.w,acc3);
        }
        const float* ja = &sH1[(lr0+0)*HST];
        const float* jb = &sH1[(lr0+1)*HST];
        const float* jc = &sH1[(lr0+2)*HST];
        const float* jd = &sH1[(lr0+3)*HST];
        #pragma unroll
        for (int k = 0; k < HID_; k += 4) {
          float w0 = sWhh1[(k+0)*G_+g], w1 = sWhh1[(k+1)*G_+g];
          float w2 = sWhh1[(k+2)*G_+g], w3 = sWhh1[(k+3)*G_+g];
          float4 va = *(const float4*)&ja[k];
          float4 vb = *(const float4*)&jb[k];
          float4 vc = *(const float4*)&jc[k];
          float4 vd = *(const float4*)&jd[k];
          acc0 = fmaf(w0,va.x,acc0); acc0 = fmaf(w1,va.y,acc0); acc0 = fmaf(w2,va.z,acc0); acc0 = fmaf(w3,va.w,acc0);
          acc1 = fmaf(w0,vb.x,acc1); acc1 = fmaf(w1,vb.y,acc1); acc1 = fmaf(w2,vb.z,acc1); acc1 = fmaf(w3,vb.w,acc1);
          acc2 = fmaf(w0,vc.x,acc2); acc2 = fmaf(w1,vc.y,acc2); acc2 = fmaf(w2,vc.z,acc2); acc2 = fmaf(w3,vc.w,acc2);
          acc3 = fmaf(w0,vd.x,acc3); acc3 = fmaf(w1,vd.y,acc3); acc3 = fmaf(w2,vd.z,acc3); acc3 = fmaf(w3,vd.w,acc3);
        }
      }
      sG[       g] = acc0; sG[  G_ + g] = acc1;
      sG[2*G_ + g] = acc2; sG[3*G_ + g] = acc3;
      __syncthreads();
      // h1/c1 update
      {
        int lr = lr0 + sr;
        float gi_ = sG[sr*G_ + ch];
        float gf  = sG[sr*G_ + 64 + ch];
        float gg  = sG[sr*G_ + 128 + ch];
        float go  = sG[sr*G_ + 192 + ch];
        float c = sigmoidf_(gf)*c1r[gi] + sigmoidf_(gi_)*tanhf(gg);
        c1r[gi] = c;
        sH1[lr*HST + ch] = sigmoidf_(go)*tanhf(c);
      }
      __syncthreads();
    }

    // --- projection + sampling for all rows of the block ---
    if (tid < 2*RPB) {
      int r = tid >> 1, pi = tid & 1;
      float d = sWp[128 + pi];
      const float* hr = &sH1[r*HST];
      const float* wp = &sWp[pi*64];
      #pragma unroll
      for (int k = 0; k < HID_; k++) d = fmaf(wp[k], hr[k], d);
      sP[tid] = d;   // tid == 2r+pi
    }
    __syncthreads();
    if (tid < nrows) {
      int lr = tid;
      int gr = row0 + lr;
      int b  = gr / NS_, s = gr % NS_;
      float p0 = sP[2*lr], p1 = sP[2*lr+1];
      float loc = fmaf(p0, sScl[lr], sCen[lr]);
      float sig = softplusf_(p1) * sScl[lr];
      float pred = fmaf(sig, g_eps[t*ROWS_TOTAL + gr], loc);
      out[(b*T_ + t)*NS_ + s] = pred;
      sLag[lr] = (pred - sCen[lr]) / sScl[lr];
    }
    __syncthreads();
  }
}

// ---------------- launch ----------------
extern "C" void kernel_launch(void* const* d_in, const int* in_sizes, int n_in,
                              void* d_out, int out_size) {
  (void)in_sizes; (void)n_in; (void)out_size;
  const float* dec_cont = (const float*)d_in[0];
  const float* one_off  = (const float*)d_in[1];
  const float* ts       = (const float*)d_in[2];
  const float* emb0     = (const float*)d_in[3];
  const float* emb1     = (const float*)d_in[4];
  const float* Wih0     = (const float*)d_in[5];
  const float* Whh0     = (const float*)d_in[6];
  const float* bih0     = (const float*)d_in[7];
  const float* bhh0     = (const float*)d_in[8];
  const float* Wih1     = (const float*)d_in[9];
  const float* Whh1     = (const float*)d_in[10];
  const float* bih1     = (const float*)d_in[11];
  const float* bhh1     = (const float*)d_in[12];
  const float* Wproj    = (const float*)d_in[13];
  const float* bproj    = (const float*)d_in[14];
  const float* h0in     = (const float*)d_in[15];
  const float* c0in     = (const float*)d_in[16];
  const int*   dec_cat  = (const int*)d_in[17];
  float* out = (float*)d_out;

  const size_t SMEM_BYTES = (size_t)(49152 + 2*RPB*HST + 1024 + 256 + 256 + 130 + 3*RPB + 2*RPB) * sizeof(float);

  eps_kernel<<<(T_*ROWS_TOTAL + 255)/256, 256>>>();
  xproj_kernel<<<B_*T_, 256>>>(dec_cont, emb0, emb1, Wih0, bih0, bhh0, dec_cat);

  cudaFuncSetAttribute(deepar_kernel, cudaFuncAttributeMaxDynamicSharedMemorySize, (int)SMEM_BYTES);
  deepar_kernel<<<NBLK, TPB, SMEM_BYTES>>>(ts, one_off, Wih0, Whh0, Wih1, Whh1,
                                           bih1, bhh1, Wproj, bproj, h0in, c0in, out);
}

// round 4
// speedup vs baseline: 1.0979x; 1.0979x over previous
#include <cuda_runtime.h>
#include <cstdint>

#define B_   128
#define T_   32
#define NS_  200
#define ROWS_TOTAL (B_*NS_)     // 25600
#define HID_ 64
#define G_   256                // 4*HID gates
#define RPB  48                 // rows per block (24 per team)
#define NBLK ((ROWS_TOTAL + RPB - 1)/RPB)   // 534
#define TPB  512                // 2 teams x 256
#define NGRP_T 6                // 4-row groups per team
#define HST  68                 // h row stride (272B, 16B aligned)

// ---------------- scratch ----------------
__device__ float g_xproj[B_*T_*G_];          // 4 MB
__device__ float g_eps[T_*ROWS_TOTAL];       // 3.125 MB

// ---------------- helpers ----------------
__device__ __forceinline__ uint32_t rotl32(uint32_t x, int d){ return (x<<d)|(x>>(32-d)); }
__device__ __forceinline__ float sigmoidf_(float x){ return 1.0f/(1.0f+expf(-x)); }
__device__ __forceinline__ float softplusf_(float x){ return fmaxf(x,0.0f) + log1pf(expf(-fabsf(x))); }

__device__ __forceinline__ uint64_t pack2(float a, float b){
  uint64_t r; asm("mov.b64 %0, {%1,%2};" : "=l"(r) : "f"(a), "f"(b)); return r;
}
__device__ __forceinline__ float hsum2(uint64_t v){
  float a,b; asm("mov.b64 {%0,%1}, %2;" : "=f"(a), "=f"(b) : "l"(v)); return a+b;
}
#define FMA2(acc, w, h) asm("fma.rn.f32x2 %0, %1, %2, %3;" : "=l"(acc) : "l"(w), "l"(h), "l"(acc))

// XLA f32 ErfInv (Giles)
__device__ __forceinline__ float erfinv_xla(float x){
  float w = -log1pf(-x*x);
  float p;
  if (w < 5.0f) {
    w = w - 2.5f;
    p = 2.81022636e-08f;
    p = fmaf(p, w, 3.43273939e-07f);
    p = fmaf(p, w, -3.5233877e-06f);
    p = fmaf(p, w, -4.39150654e-06f);
    p = fmaf(p, w, 0.00021858087f);
    p = fmaf(p, w, -0.00125372503f);
    p = fmaf(p, w, -0.00417768164f);
    p = fmaf(p, w, 0.246640727f);
    p = fmaf(p, w, 1.50140941f);
  } else {
    w = sqrtf(w) - 3.0f;
    p = -0.000200214257f;
    p = fmaf(p, w, 0.000100950558f);
    p = fmaf(p, w, 0.00134934322f);
    p = fmaf(p, w, -0.00367342844f);
    p = fmaf(p, w, 0.00573950773f);
    p = fmaf(p, w, -0.0076224613f);
    p = fmaf(p, w, 0.00943887047f);
    p = fmaf(p, w, 1.00167406f);
    p = fmaf(p, w, 2.83297682f);
  }
  return p * x;
}

__device__ __forceinline__ float bits_to_normal(uint32_t bits){
  float u = __uint_as_float((bits>>9) | 0x3f800000u) - 1.0f;
  float x = fmaf(u, 2.0f, -0.99999994f);
  x = fmaxf(-0.99999994f, x);
  return 1.41421356f * erfinv_xla(x);
}

// ---------------- eps: partitionable Threefry, bits1^bits2 ----------------
__global__ void eps_kernel(){
  const uint32_t N = (uint32_t)(T_*ROWS_TOTAL);
  uint32_t j = blockIdx.x*blockDim.x + threadIdx.x;
  if (j >= N) return;
  const uint32_t ks0 = 0u, ks1 = 42u, ks2 = 0x1BD11BDAu ^ 42u;
  uint32_t x0 = 0u, x1 = j;
  x0 += ks0; x1 += ks1;
#define RND_(r) { x0 += x1; x1 = rotl32(x1, (r)); x1 ^= x0; }
  RND_(13) RND_(15) RND_(26) RND_(6)   x0 += ks1; x1 += ks2 + 1u;
  RND_(17) RND_(29) RND_(16) RND_(24)  x0 += ks2; x1 += ks0 + 2u;
  RND_(13) RND_(15) RND_(26) RND_(6)   x0 += ks0; x1 += ks1 + 3u;
  RND_(17) RND_(29) RND_(16) RND_(24)  x0 += ks1; x1 += ks2 + 4u;
  RND_(13) RND_(15) RND_(26) RND_(6)   x0 += ks2; x1 += ks0 + 5u;
#undef RND_
  g_eps[j] = bits_to_normal(x0 ^ x1);
}

// ---------------- xproj ----------------
__global__ void xproj_kernel(const float* __restrict__ dec_cont,
                             const float* __restrict__ emb0,
                             const float* __restrict__ emb1,
                             const float* __restrict__ Wih0,
                             const float* __restrict__ bih0,
                             const float* __restrict__ bhh0,
                             const int*   __restrict__ dec_cat){
  int bt = blockIdx.x;
  int g  = threadIdx.x;
  __shared__ float feat[32];
  if (g < 32) {
    float v = 0.0f;
    if (g >= 1 && g < 6) {
      v = dec_cont[bt*6 + g];
    } else if (g >= 6 && g < 16) {
      int c0 = dec_cat[bt*2 + 0];
      v = emb0[c0*10 + (g-6)];
    } else if (g >= 16) {
      int c1 = dec_cat[bt*2 + 1];
      v = emb1[c1*16 + (g-16)];
    }
    feat[g] = v;
  }
  __syncthreads();
  float acc = bih0[g] + bhh0[g];
  #pragma unroll
  for (int k = 1; k < 32; k++) acc = fmaf(Wih0[g*32 + k], feat[k], acc);
  g_xproj[bt*G_ + g] = acc;
}

// ---------------- main persistent LSTM kernel ----------------
__global__ __launch_bounds__(TPB, 1)
void deepar_kernel(const float* __restrict__ ts,
                   const float* __restrict__ one_off,
                   const float* __restrict__ Wih0,
                   const float* __restrict__ Whh0,
                   const float* __restrict__ Wih1,
                   const float* __restrict__ Whh1,
                   const float* __restrict__ bih1,
                   const float* __restrict__ bhh1,
                   const float* __restrict__ Wproj,
                   const float* __restrict__ bproj,
                   const float* __restrict__ h0in,
                   const float* __restrict__ c0in,
                   float* __restrict__ out)
{
  extern __shared__ float sm[];
  float* sWhh0 = sm;                   // [16][256*4] chunk-major: c*1024 + 4*g
  float* sWih1 = sm + 16384;
  float* sWhh1 = sm + 32768;
  float* sH0   = sm + 49152;           // [2*4][HST]
  float* sH1   = sH0 + 8*HST;          // [2*4][HST]
  float* sG    = sH1 + 8*HST;          // [2][4][256]
  float* sRed  = sG + 2048;            // [2][4][2][2]
  float* sLagS = sRed + 32;            // [2][4]
  // total floats = 49152 + 544 + 544 + 2048 + 32 + 8 = 52328 (209312 B)

  const int tid  = threadIdx.x;
  const int team = tid >> 8;
  const int tt   = tid & 255;
  const int g    = tt;
  const int sr   = tt >> 6, ch = tt & 63;
  const int row0 = blockIdx.x * RPB;

  // --- weights: chunk-major float4 copy (LDS.128-friendly, conflict-free) ---
  if (team == 0) {
    #pragma unroll
    for (int c = 0; c < 16; c++) {
      *(float4*)&sWhh0[c*1024 + 4*g] = *(const float4*)&Whh0[g*64 + 4*c];
      *(float4*)&sWih1[c*1024 + 4*g] = *(const float4*)&Wih1[g*64 + 4*c];
    }
  } else {
    #pragma unroll
    for (int c = 0; c < 16; c++)
      *(float4*)&sWhh1[c*1024 + 4*g] = *(const float4*)&Whh1[g*64 + 4*c];
  }
  const float w0c = Wih0[g*32];           // column 0 of layer0 input weights
  const float bl1 = bih1[g] + bhh1[g];
  const float wp0 = Wproj[ch], wp1 = Wproj[64 + ch];
  const float bp0 = bproj[0],  bp1 = bproj[1];
  __syncthreads();

#define TBAR() asm volatile("bar.sync %0, 256;" :: "r"(team+1) : "memory")

  float* sGt = sG + team*1024;
  float* hb0 = sH0 + team*4*HST;
  float* hb1 = sH1 + team*4*HST;
  float* red = sRed + team*16;
  float* lag = sLagS + team*4;

  #pragma unroll 1
  for (int gi = 0; gi < NGRP_T; gi++) {
    const int gr0 = row0 + team*24 + gi*4;
    const int myrow = gr0 + sr;
    const bool valid = myrow < ROWS_TOTAL;
    const int mb = (valid ? myrow : ROWS_TOTAL-1) / NS_;

    // per-group state init
    float c0v = valid ? c0in[mb*HID_ + ch] : 0.f;
    float c1v = valid ? c0in[B_*HID_ + mb*HID_ + ch] : 0.f;
    hb0[sr*HST + ch] = valid ? h0in[mb*HID_ + ch] : 0.f;
    hb1[sr*HST + ch] = valid ? h0in[B_*HID_ + mb*HID_ + ch] : 0.f;
    if (tt < 4) {
      int r = gr0 + tt; bool v = r < ROWS_TOTAL;
      int b = (v ? r : ROWS_TOTAL-1)/NS_;
      lag[tt] = v ? one_off[b] : 0.f;
    }
    const float cen = valid ? ts[2*mb]   : 0.f;
    const float scl = valid ? ts[2*mb+1] : 1.f;

    // xproj row pointers (+ first-t prefetch)
    const int q0 = min(gr0+0, ROWS_TOTAL-1)/NS_;
    const int q1 = min(gr0+1, ROWS_TOTAL-1)/NS_;
    const int q2 = min(gr0+2, ROWS_TOTAL-1)/NS_;
    const int q3 = min(gr0+3, ROWS_TOTAL-1)/NS_;
    const float* xpp0 = g_xproj + q0*T_*G_ + g;
    const float* xpp1 = g_xproj + q1*T_*G_ + g;
    const float* xpp2 = g_xproj + q2*T_*G_ + g;
    const float* xpp3 = g_xproj + q3*T_*G_ + g;
    float xq0 = xpp0[0], xq1 = xpp1[0], xq2 = xpp2[0], xq3 = xpp3[0];

    const int egr = valid ? myrow : 0;
    float ecur = 0.f;
    if (ch == 0) ecur = g_eps[egr];     // eps(t=0)
    TBAR();

    #pragma unroll 1
    for (int t = 0; t < T_; t++) {
      const int tn = (t+1 < T_) ? t+1 : t;
      // ---- layer0 gates: xproj + w0c*lag + Whh0 @ h0 ----
      uint64_t a0 = pack2(fmaf(w0c, lag[0], xq0), 0.f);
      uint64_t a1 = pack2(fmaf(w0c, lag[1], xq1), 0.f);
      uint64_t a2 = pack2(fmaf(w0c, lag[2], xq2), 0.f);
      uint64_t a3 = pack2(fmaf(w0c, lag[3], xq3), 0.f);
      // prefetch next-t xproj (off critical path)
      xq0 = xpp0[tn*G_]; xq1 = xpp1[tn*G_]; xq2 = xpp2[tn*G_]; xq3 = xpp3[tn*G_];
      #pragma unroll
      for (int c = 0; c < 16; c++) {
        ulonglong2 w  = *(const ulonglong2*)&sWhh0[c*1024 + 4*g];
        ulonglong2 hA = *(const ulonglong2*)&hb0[0*HST + 4*c];
        ulonglong2 hB = *(const ulonglong2*)&hb0[1*HST + 4*c];
        ulonglong2 hC = *(const ulonglong2*)&hb0[2*HST + 4*c];
        ulonglong2 hD = *(const ulonglong2*)&hb0[3*HST + 4*c];
        FMA2(a0, w.x, hA.x); FMA2(a0, w.y, hA.y);
        FMA2(a1, w.x, hB.x); FMA2(a1, w.y, hB.y);
        FMA2(a2, w.x, hC.x); FMA2(a2, w.y, hC.y);
        FMA2(a3, w.x, hD.x); FMA2(a3, w.y, hD.y);
      }
      sGt[      g] = hsum2(a0);
      sGt[256 + g] = hsum2(a1);
      sGt[512 + g] = hsum2(a2);
      sGt[768 + g] = hsum2(a3);
      TBAR();
      // ---- h0/c0 update ----
      {
        float xi = sGt[sr*256 +       ch];
        float xf = sGt[sr*256 +  64 + ch];
        float xg = sGt[sr*256 + 128 + ch];
        float xo = sGt[sr*256 + 192 + ch];
        c0v = sigmoidf_(xf)*c0v + sigmoidf_(xi)*tanhf(xg);
        hb0[sr*HST + ch] = sigmoidf_(xo)*tanhf(c0v);
      }
      TBAR();
      // ---- layer1 gates: b1 + Wih1 @ h0_new + Whh1 @ h1 ----
      a0 = pack2(bl1, 0.f); a1 = a0; a2 = a0; a3 = a0;
      #pragma unroll
      for (int c = 0; c < 16; c++) {
        ulonglong2 wI = *(const ulonglong2*)&sWih1[c*1024 + 4*g];
        ulonglong2 wH = *(const ulonglong2*)&sWhh1[c*1024 + 4*g];
        ulonglong2 hA = *(const ulonglong2*)&hb0[0*HST + 4*c];
        ulonglong2 hB = *(const ulonglong2*)&hb0[1*HST + 4*c];
        ulonglong2 hC = *(const ulonglong2*)&hb0[2*HST + 4*c];
        ulonglong2 hD = *(const ulonglong2*)&hb0[3*HST + 4*c];
        FMA2(a0, wI.x, hA.x); FMA2(a0, wI.y, hA.y);
        FMA2(a1, wI.x, hB.x); FMA2(a1, wI.y, hB.y);
        FMA2(a2, wI.x, hC.x); FMA2(a2, wI.y, hC.y);
        FMA2(a3, wI.x, hD.x); FMA2(a3, wI.y, hD.y);
        ulonglong2 jA = *(const ulonglong2*)&hb1[0*HST + 4*c];
        ulonglong2 jB = *(const ulonglong2*)&hb1[1*HST + 4*c];
        ulonglong2 jC = *(const ulonglong2*)&hb1[2*HST + 4*c];
        ulonglong2 jD = *(const ulonglong2*)&hb1[3*HST + 4*c];
        FMA2(a0, wH.x, jA.x); FMA2(a0, wH.y, jA.y);
        FMA2(a1, wH.x, jB.x); FMA2(a1, wH.y, jB.y);
        FMA2(a2, wH.x, jC.x); FMA2(a2, wH.y, jC.y);
        FMA2(a3, wH.x, jD.x); FMA2(a3, wH.y, jD.y);
      }
      sGt[      g] = hsum2(a0);
      sGt[256 + g] = hsum2(a1);
      sGt[512 + g] = hsum2(a2);
      sGt[768 + g] = hsum2(a3);
      TBAR();
      // ---- h1/c1 update + fused projection partials ----
      float h1v;
      {
        float xi = sGt[sr*256 +       ch];
        float xf = sGt[sr*256 +  64 + ch];
        float xg = sGt[sr*256 + 128 + ch];
        float xo = sGt[sr*256 + 192 + ch];
        c1v = sigmoidf_(xf)*c1v + sigmoidf_(xi)*tanhf(xg);
        h1v = sigmoidf_(xo)*tanhf(c1v);
        hb1[sr*HST + ch] = h1v;
      }
      float p0 = wp0*h1v, p1 = wp1*h1v;
      #pragma unroll
      for (int off = 16; off; off >>= 1) {
        p0 += __shfl_xor_sync(0xffffffffu, p0, off);
        p1 += __shfl_xor_sync(0xffffffffu, p1, off);
      }
      if ((tt & 31) == 0) {
        int half = (tt >> 5) & 1;
        red[sr*4 + half*2 + 0] = p0;
        red[sr*4 + half*2 + 1] = p1;
      }
      TBAR();
      // ---- combine + sample (one thread per row: ch==0) ----
      if (ch == 0) {
        float r0 = red[sr*4 + 0] + red[sr*4 + 2] + bp0;
        float r1 = red[sr*4 + 1] + red[sr*4 + 3] + bp1;
        float loc  = fmaf(r0, scl, cen);
        float sig  = softplusf_(r1) * scl;
        float pred = fmaf(sig, ecur, loc);
        if (valid) {
          int s = myrow - mb*NS_;
          out[(mb*T_ + t)*NS_ + s] = pred;
        }
        lag[sr] = (pred - cen) / scl;
        ecur = g_eps[tn*ROWS_TOTAL + egr];   // prefetch eps(t+1)
      }
      TBAR();
    }
  }
#undef TBAR
}

// ---------------- launch ----------------
extern "C" void kernel_launch(void* const* d_in, const int* in_sizes, int n_in,
                              void* d_out, int out_size) {
  (void)in_sizes; (void)n_in; (void)out_size;
  const float* dec_cont = (const float*)d_in[0];
  const float* one_off  = (const float*)d_in[1];
  const float* ts       = (const float*)d_in[2];
  const float* emb0     = (const float*)d_in[3];
  const float* emb1     = (const float*)d_in[4];
  const float* Wih0     = (const float*)d_in[5];
  const float* Whh0     = (const float*)d_in[6];
  const float* bih0     = (const float*)d_in[7];
  const float* bhh0     = (const float*)d_in[8];
  const float* Wih1     = (const float*)d_in[9];
  const float* Whh1     = (const float*)d_in[10];
  const float* bih1     = (const float*)d_in[11];
  const float* bhh1     = (const float*)d_in[12];
  const float* Wproj    = (const float*)d_in[13];
  const float* bproj    = (const float*)d_in[14];
  const float* h0in     = (const float*)d_in[15];
  const float* c0in     = (const float*)d_in[16];
  const int*   dec_cat  = (const int*)d_in[17];
  float* out = (float*)d_out;

  const size_t SMEM_BYTES = (size_t)(49152 + 2*8*HST + 2048 + 32 + 8) * sizeof(float);

  eps_kernel<<<(T_*ROWS_TOTAL + 255)/256, 256>>>();
  xproj_kernel<<<B_*T_, 256>>>(dec_cont, emb0, emb1, Wih0, bih0, bhh0, dec_cat);

  cudaFuncSetAttribute(deepar_kernel, cudaFuncAttributeMaxDynamicSharedMemorySize, (int)SMEM_BYTES);
  deepar_kernel<<<NBLK, TPB, SMEM_BYTES>>>(ts, one_off, Wih0, Whh0, Wih1, Whh1,
                                           bih1, bhh1, Wproj, bproj, h0in, c0in, out);
}